// round 1
// baseline (speedup 1.0000x reference)
#include <cuda_runtime.h>
#include <cuda_bf16.h>
#include <cstdint>

// Problem constants
#define Bsz 16
#define Cch 256
#define Hh 48
#define Ww 160
#define HW (Hh*Ww)          // 7680
#define MM 256
#define KK 256

// Scratch (device globals; no allocation allowed)
__device__ float  g_G[(size_t)Bsz * MM * HW];   // 125.8 MB: per-row channel-mixed features
__device__ float  g_A[MM * KK];                 // repacked w_ext[:,1:257]
__device__ float4 g_px[Bsz * HW];               // per-pixel (iy0, wy, dsamp, _)

// ---------------------------------------------------------------------------
// f32x2 packed helpers
// ---------------------------------------------------------------------------
__device__ __forceinline__ unsigned long long dup2(float x) {
    unsigned long long r;
    asm("mov.b64 %0, {%1, %1};" : "=l"(r) : "f"(x));
    return r;
}
__device__ __forceinline__ void fma2(unsigned long long& d, unsigned long long a, unsigned long long b) {
    asm("fma.rn.f32x2 %0, %1, %2, %0;" : "+l"(d) : "l"(a), "l"(b));
}

// ---------------------------------------------------------------------------
// Kernel 0: repack A[o][c] = w_ext[o, 1+c]  (row stride 257 -> 256 contiguous)
// ---------------------------------------------------------------------------
__global__ void prepA_kernel(const float* __restrict__ w_ext) {
    int i = blockIdx.x * blockDim.x + threadIdx.x;
    if (i < MM * KK) {
        int m = i >> 8, c = i & 255;
        g_A[i] = w_ext[m * 257 + 1 + c];
    }
}

// ---------------------------------------------------------------------------
// Kernel 1: 3x3 conv (256ch -> 1) + tanh -> disp; per-pixel gy -> (iy0, wy)
//           and interpolated disparity channel dsamp.
// grid = B * 12 (4 output rows per block), block = 160 threads (one per w)
// ---------------------------------------------------------------------------
__global__ void prep_kernel(const float* __restrict__ feats,
                            const float* __restrict__ P2,
                            const float* __restrict__ w_disp,
                            const float* __restrict__ b_disp) {
    const int blk = blockIdx.x;
    const int b  = blk / 12;
    const int y0 = (blk % 12) * 4;
    const int tid = threadIdx.x;   // w in [0,160)

    __shared__ float sw[Cch * 9];
    __shared__ float srow[6][Ww];

    for (int i = tid; i < Cch * 9; i += 160) sw[i] = w_disp[i];

    float acc0 = 0.f, acc1 = 0.f, acc2 = 0.f, acc3 = 0.f;
    const float* Fb = feats + (size_t)b * Cch * HW;
    __syncthreads();

    for (int c = 0; c < Cch; ++c) {
        const float* Fc = Fb + (size_t)c * HW;
#pragma unroll
        for (int r = 0; r < 6; ++r) {
            int yy = y0 - 1 + r;
            srow[r][tid] = (yy >= 0 && yy < Hh) ? Fc[yy * Ww + tid] : 0.f;
        }
        __syncthreads();

        float v[6][3];
#pragma unroll
        for (int r = 0; r < 6; ++r) {
            v[r][0] = (tid > 0)       ? srow[r][tid - 1] : 0.f;
            v[r][1] =                   srow[r][tid];
            v[r][2] = (tid < Ww - 1)  ? srow[r][tid + 1] : 0.f;
        }
        const float* wc = &sw[c * 9];
#pragma unroll
        for (int ky = 0; ky < 3; ++ky) {
#pragma unroll
            for (int kx = 0; kx < 3; ++kx) {
                float wv = wc[ky * 3 + kx];
                acc0 = fmaf(v[0 + ky][kx], wv, acc0);
                acc1 = fmaf(v[1 + ky][kx], wv, acc1);
                acc2 = fmaf(v[2 + ky][kx], wv, acc2);
                acc3 = fmaf(v[3 + ky][kx], wv, acc3);
            }
        }
        __syncthreads();
    }

    // Per-batch scalars (P2 rows 0:2 divided by 16; only row-1 entries used)
    const float fy = P2[b * 12 + 5] * 0.0625f;
    const float cy = P2[b * 12 + 6] * 0.0625f;
    const float Ty = P2[b * 12 + 7] * 0.0625f;
    const float bd = b_disp[0];
    const float denomD = fabsf(fy * 1.65f + Ty) + 1e-10f;
    const float ysb_den = 2.f * (1.65f - 0.5f * 1.535f);   // 1.765

    float accs[4] = {acc0, acc1, acc2, acc3};
#pragma unroll
    for (int ry = 0; ry < 4; ++ry) {
        int y = y0 + ry;
        float d    = tanhf(accs[ry] + bd);
        float disp = 0.1f * d;                             // 0.1*(0.05*d+0.95*sg(d))
        float ybase = -1.f + 2.f * (float)y / 47.f;
        float ysb = fmaxf(1.535f * ((float)y - cy) / ysb_den, 0.f) * (1.f / 24.f);
        float gy = ybase + ysb + disp;
        float iy = fminf(fmaxf((gy + 1.f) * 23.5f, 0.f), 47.f);
        float iy0f = floorf(iy);
        float wy = iy - iy0f;
        int iy0 = (int)iy0f;
        int iy1 = min(iy0 + 1, Hh - 1);
        float d0 = fmaxf(fy * 0.54f * ((float)iy0 - cy) / denomD, 0.f);
        float d1 = fmaxf(fy * 0.54f * ((float)iy1 - cy) / denomD, 0.f);
        float ds = (1.f - wy) * d0 + wy * d1;
        g_px[((size_t)b * Hh + y) * Ww + tid] = make_float4(iy0f, wy, ds, 0.f);
    }
}

// ---------------------------------------------------------------------------
// Kernel 2: batched GEMM  G[b] = A(256x256) * F[b](256x7680)
// BM=BN=128, BK=16, 256 threads, 8x8 per thread, packed f32x2 FMA.
// grid = (60, 2, 16)
// ---------------------------------------------------------------------------
__global__ void __launch_bounds__(256)
gemm_kernel(const float* __restrict__ feats) {
    __shared__ float As[16][128];
    __shared__ float Bs[16][128];

    const int b  = blockIdx.z;
    const int mt = blockIdx.y;
    const int nt = blockIdx.x;
    const int tid = threadIdx.x;
    const int tx = tid & 15;     // N direction: 8 cols each
    const int ty = tid >> 4;     // M direction: 8 rows each

    const float* Bg = feats + (size_t)b * KK * HW + nt * 128;
    float*       Cg = g_G   + (size_t)b * MM * HW + (size_t)(mt * 128) * HW + nt * 128;

    const int mA = tid >> 1;            // 0..127
    const int kA = (tid & 1) * 8;       // 0 or 8

    unsigned long long acc[8][4];
#pragma unroll
    for (int i = 0; i < 8; ++i)
#pragma unroll
        for (int j = 0; j < 4; ++j) acc[i][j] = 0ULL;

    for (int kt = 0; kt < KK / 16; ++kt) {
        const int k0 = kt * 16;
        // Load A tile (store transposed: As[k][m])
        float4 a0 = *(const float4*)&g_A[(size_t)(mt * 128 + mA) * KK + k0 + kA];
        float4 a1 = *(const float4*)&g_A[(size_t)(mt * 128 + mA) * KK + k0 + kA + 4];
        As[kA + 0][mA] = a0.x; As[kA + 1][mA] = a0.y;
        As[kA + 2][mA] = a0.z; As[kA + 3][mA] = a0.w;
        As[kA + 4][mA] = a1.x; As[kA + 5][mA] = a1.y;
        As[kA + 6][mA] = a1.z; As[kA + 7][mA] = a1.w;
        // Load B tile
#pragma unroll
        for (int i = 0; i < 2; ++i) {
            int e  = tid + 256 * i;
            int kB = e >> 5;
            int nB = (e & 31) * 4;
            *(float4*)&Bs[kB][nB] = *(const float4*)&Bg[(size_t)(k0 + kB) * HW + nB];
        }
        __syncthreads();

#pragma unroll
        for (int k = 0; k < 16; ++k) {
            float4 af0 = *(const float4*)&As[k][ty * 8];
            float4 af1 = *(const float4*)&As[k][ty * 8 + 4];
            ulonglong2 bv0 = *(const ulonglong2*)&Bs[k][tx * 8];
            ulonglong2 bv1 = *(const ulonglong2*)&Bs[k][tx * 8 + 4];
            unsigned long long bb0 = bv0.x, bb1 = bv0.y, bb2 = bv1.x, bb3 = bv1.y;
            float a[8] = {af0.x, af0.y, af0.z, af0.w, af1.x, af1.y, af1.z, af1.w};
#pragma unroll
            for (int m = 0; m < 8; ++m) {
                unsigned long long ap = dup2(a[m]);
                fma2(acc[m][0], ap, bb0);
                fma2(acc[m][1], ap, bb1);
                fma2(acc[m][2], ap, bb2);
                fma2(acc[m][3], ap, bb3);
            }
        }
        __syncthreads();
    }

    // Epilogue: packed ull bit layout == float2{lo,hi} in memory
#pragma unroll
    for (int i = 0; i < 8; ++i) {
        float* cp = Cg + (size_t)(ty * 8 + i) * HW + tx * 8;
        *(ulonglong2*)(cp)     = make_ulonglong2(acc[i][0], acc[i][1]);
        *(ulonglong2*)(cp + 4) = make_ulonglong2(acc[i][2], acc[i][3]);
    }
}

// ---------------------------------------------------------------------------
// Kernel 3: out = relu(x + alpha*((1-wy)*G[iy0] + wy*G[iy1] + w_ext[o,0]*dsamp + b_ext))
// grid = B*H (one block per output row), block = 256 (8 o-groups x 32 lanes)
// ---------------------------------------------------------------------------
__global__ void final_kernel(const float* __restrict__ feats,
                             const float* __restrict__ w_ext,
                             const float* __restrict__ b_ext,
                             const float* __restrict__ alpha,
                             float* __restrict__ out) {
    const int blk = blockIdx.x;
    const int b = blk / Hh;
    const int y = blk % Hh;
    const int tid = threadIdx.x;

    __shared__ float s_iy0[Ww], s_wy[Ww], s_ds[Ww];
    if (tid < Ww) {
        float4 p = g_px[((size_t)b * Hh + y) * Ww + tid];
        s_iy0[tid] = p.x; s_wy[tid] = p.y; s_ds[tid] = p.z;
    }
    __syncthreads();

    const float al = alpha[0];
    const int wl = tid & 31;
    const int og = tid >> 5;   // 0..7

    const float* Gb = g_G   + (size_t)b * MM * HW;
    const float* Fb = feats + (size_t)b * Cch * HW;
    float*       Ob = out   + (size_t)b * Cch * HW;

    for (int o = og; o < MM; o += 8) {
        const float we0 = w_ext[o * 257];
        const float be  = b_ext[o];
        const float* Gp = Gb + (size_t)o * HW;
        const float* Fp = Fb + (size_t)o * HW + y * Ww;
        float*       Op = Ob + (size_t)o * HW + y * Ww;
#pragma unroll
        for (int w = wl; w < Ww; w += 32) {
            int   iy0 = (int)s_iy0[w];
            float wy  = s_wy[w];
            int   iy1 = min(iy0 + 1, Hh - 1);
            float g = Gp[iy0 * Ww + w] * (1.f - wy) + Gp[iy1 * Ww + w] * wy;
            float v = g + we0 * s_ds[w] + be;
            float r = fmaf(v, al, Fp[w]);
            Op[w] = fmaxf(r, 0.f);
        }
    }
}

// ---------------------------------------------------------------------------
extern "C" void kernel_launch(void* const* d_in, const int* in_sizes, int n_in,
                              void* d_out, int out_size) {
    const float* feats  = (const float*)d_in[0];
    const float* P2     = (const float*)d_in[1];
    const float* w_disp = (const float*)d_in[2];
    const float* b_disp = (const float*)d_in[3];
    const float* w_ext  = (const float*)d_in[4];
    const float* b_ext  = (const float*)d_in[5];
    const float* alpha  = (const float*)d_in[6];
    float* out = (float*)d_out;

    prepA_kernel<<<256, 256>>>(w_ext);
    prep_kernel<<<Bsz * 12, 160>>>(feats, P2, w_disp, b_disp);
    gemm_kernel<<<dim3(HW / 128, MM / 128, Bsz), 256>>>(feats);
    final_kernel<<<Bsz * Hh, 256>>>(feats, w_ext, b_ext, alpha, out);
}

// round 2
// speedup vs baseline: 1.1810x; 1.1810x over previous
#include <cuda_runtime.h>
#include <cuda_bf16.h>
#include <cstdint>

// Problem constants
#define Bsz 16
#define Cch 256
#define Hh 48
#define Ww 160
#define HW (Hh*Ww)          // 7680
#define MM 256
#define KK 256

// Scratch (device globals; no allocation allowed)
__device__ float  g_A[MM * KK];                 // repacked w_ext[:,1:257]
__device__ float4 g_px[Bsz * HW];               // per-pixel (iy0, wy, dsamp, _)

// ---------------------------------------------------------------------------
// f32x2 packed helpers
// ---------------------------------------------------------------------------
__device__ __forceinline__ unsigned long long dup2(float x) {
    unsigned long long r;
    asm("mov.b64 %0, {%1, %1};" : "=l"(r) : "f"(x));
    return r;
}
__device__ __forceinline__ void fma2(unsigned long long& d, unsigned long long a, unsigned long long b) {
    asm("fma.rn.f32x2 %0, %1, %2, %0;" : "+l"(d) : "l"(a), "l"(b));
}
__device__ __forceinline__ float2 u2f(unsigned long long v) {
    float2 r;
    asm("mov.b64 {%0, %1}, %2;" : "=f"(r.x), "=f"(r.y) : "l"(v));
    return r;
}

// ---------------------------------------------------------------------------
// Kernel 0: repack A[o][c] = w_ext[o, 1+c]
// ---------------------------------------------------------------------------
__global__ void prepA_kernel(const float* __restrict__ w_ext) {
    int i = blockIdx.x * blockDim.x + threadIdx.x;
    if (i < MM * KK) {
        int m = i >> 8, c = i & 255;
        g_A[i] = w_ext[m * 257 + 1 + c];
    }
}

// ---------------------------------------------------------------------------
// Kernel 1: 3x3 conv (256ch -> 1) + tanh -> disp; per-pixel (iy0, wy, dsamp).
// grid = B * 12 (4 output rows per block), block = (160, 4):
// 4 channel-groups of 64 channels each, reduced in smem at the end.
// ---------------------------------------------------------------------------
__global__ void __launch_bounds__(640)
prep_kernel(const float* __restrict__ feats,
            const float* __restrict__ P2,
            const float* __restrict__ w_disp,
            const float* __restrict__ b_disp) {
    const int blk = blockIdx.x;
    const int b  = blk / 12;
    const int y0 = (blk % 12) * 4;
    const int wx = threadIdx.x;            // 0..159
    const int g  = threadIdx.y;            // 0..3 channel group
    const int tid = wx + 160 * g;

    __shared__ float sw[Cch * 9];
    __shared__ float srow[4][6][Ww];
    __shared__ float red[4][4][Ww];

    for (int i = tid; i < Cch * 9; i += 640) sw[i] = w_disp[i];

    float acc0 = 0.f, acc1 = 0.f, acc2 = 0.f, acc3 = 0.f;
    const float* Fb = feats + (size_t)b * Cch * HW;
    __syncthreads();

    for (int cc = 0; cc < 64; ++cc) {
        const int c = g * 64 + cc;
        const float* Fc = Fb + (size_t)c * HW;
#pragma unroll
        for (int r = 0; r < 6; ++r) {
            int yy = y0 - 1 + r;
            srow[g][r][wx] = (yy >= 0 && yy < Hh) ? Fc[yy * Ww + wx] : 0.f;
        }
        __syncthreads();

        float v[6][3];
#pragma unroll
        for (int r = 0; r < 6; ++r) {
            v[r][0] = (wx > 0)      ? srow[g][r][wx - 1] : 0.f;
            v[r][1] =                 srow[g][r][wx];
            v[r][2] = (wx < Ww - 1) ? srow[g][r][wx + 1] : 0.f;
        }
        const float* wc = &sw[c * 9];
#pragma unroll
        for (int ky = 0; ky < 3; ++ky) {
#pragma unroll
            for (int kx = 0; kx < 3; ++kx) {
                float wv = wc[ky * 3 + kx];
                acc0 = fmaf(v[0 + ky][kx], wv, acc0);
                acc1 = fmaf(v[1 + ky][kx], wv, acc1);
                acc2 = fmaf(v[2 + ky][kx], wv, acc2);
                acc3 = fmaf(v[3 + ky][kx], wv, acc3);
            }
        }
        __syncthreads();
    }

    red[g][0][wx] = acc0;
    red[g][1][wx] = acc1;
    red[g][2][wx] = acc2;
    red[g][3][wx] = acc3;
    __syncthreads();

    if (g == 0) {
        // Per-batch scalars (P2 rows 0:2 divided by 16; only row-1 entries used)
        const float fy = P2[b * 12 + 5] * 0.0625f;
        const float cy = P2[b * 12 + 6] * 0.0625f;
        const float Ty = P2[b * 12 + 7] * 0.0625f;
        const float bd = b_disp[0];
        const float denomD = fabsf(fy * 1.65f + Ty) + 1e-10f;
        const float ysb_den = 2.f * (1.65f - 0.5f * 1.535f);   // 1.765

#pragma unroll
        for (int ry = 0; ry < 4; ++ry) {
            int y = y0 + ry;
            float a = red[0][ry][wx] + red[1][ry][wx] + red[2][ry][wx] + red[3][ry][wx];
            float d    = tanhf(a + bd);
            float disp = 0.1f * d;
            float ybase = -1.f + 2.f * (float)y / 47.f;
            float ysb = fmaxf(1.535f * ((float)y - cy) / ysb_den, 0.f) * (1.f / 24.f);
            float gy = ybase + ysb + disp;
            float iy = fminf(fmaxf((gy + 1.f) * 23.5f, 0.f), 47.f);
            float iy0f = floorf(iy);
            float wy = iy - iy0f;
            int iy0 = (int)iy0f;
            int iy1 = min(iy0 + 1, Hh - 1);
            float d0 = fmaxf(fy * 0.54f * ((float)iy0 - cy) / denomD, 0.f);
            float d1 = fmaxf(fy * 0.54f * ((float)iy1 - cy) / denomD, 0.f);
            float ds = (1.f - wy) * d0 + wy * d1;
            g_px[((size_t)b * Hh + y) * Ww + wx] = make_float4(iy0f, wy, ds, 0.f);
        }
    }
}

// ---------------------------------------------------------------------------
// Kernel 2: fused sampled-GEMM + epilogue.
//  out[b,o,n] = relu(x[b,o,n] + alpha*( Σ_c A[o,c]*Fsamp[b,c,n]
//                                       + w_ext[o,0]*ds[b,n] + b_ext[o] ))
//  Fsamp gathered+blended at B-tile load time.
//  BM=BN=128, BK=16, 256 threads, 8x8 per thread, packed f32x2 FMA.
//  grid = (60, 2, 16)
// ---------------------------------------------------------------------------
__global__ void __launch_bounds__(256)
gemm_fused(const float* __restrict__ feats,
           const float* __restrict__ w_ext,
           const float* __restrict__ b_ext,
           const float* __restrict__ alpha,
           float* __restrict__ out) {
    __shared__ float As[16][128];
    __shared__ float Bs[16][128];
    __shared__ int   s_o0[128], s_o1[128];
    __shared__ float s_wy[128], s_ds[128];
    __shared__ float s_we0[128], s_be[128];

    const int b  = blockIdx.z;
    const int mt = blockIdx.y;
    const int nt = blockIdx.x;
    const int tid = threadIdx.x;
    const int tx = tid & 15;     // N direction: 8 cols each
    const int ty = tid >> 4;     // M direction: 8 rows each
    const int n0 = nt * 128;

    if (tid < 128) {
        int n = n0 + tid;
        float4 px = g_px[(size_t)b * HW + n];
        int iy0 = (int)px.x;
        int iy1 = min(iy0 + 1, Hh - 1);
        int w = n % Ww;
        s_o0[tid] = iy0 * Ww + w;
        s_o1[tid] = iy1 * Ww + w;
        s_wy[tid] = px.y;
        s_ds[tid] = px.z;
        int m = mt * 128 + tid;
        s_we0[tid] = w_ext[m * 257];
        s_be[tid]  = b_ext[m];
    }

    const float* Fb = feats + (size_t)b * Cch * HW;

    const int mA  = tid >> 1;            // 0..127
    const int kA  = (tid & 1) * 8;       // 0 or 8
    const int pB  = tid & 127;           // pixel within tile
    const int kB0 = (tid >> 7) * 8;      // 0 or 8

    unsigned long long acc[8][4];
#pragma unroll
    for (int i = 0; i < 8; ++i)
#pragma unroll
        for (int j = 0; j < 4; ++j) acc[i][j] = 0ULL;

    __syncthreads();

    for (int kt = 0; kt < KK / 16; ++kt) {
        const int k0 = kt * 16;
        // A tile (store transposed: As[k][m])
        float4 a0 = *(const float4*)&g_A[(size_t)(mt * 128 + mA) * KK + k0 + kA];
        float4 a1 = *(const float4*)&g_A[(size_t)(mt * 128 + mA) * KK + k0 + kA + 4];
        // B tile: gather rows iy0/iy1 and blend (vertical interpolation)
        const int   o0 = s_o0[pB];
        const int   o1 = s_o1[pB];
        const float wy = s_wy[pB];
        const float* Fk = Fb + (size_t)(k0 + kB0) * HW;
        float bsv[8];
#pragma unroll
        for (int j = 0; j < 8; ++j) {
            float f0 = Fk[(size_t)j * HW + o0];
            float f1 = Fk[(size_t)j * HW + o1];
            bsv[j] = f0 * (1.f - wy) + f1 * wy;
        }
        As[kA + 0][mA] = a0.x; As[kA + 1][mA] = a0.y;
        As[kA + 2][mA] = a0.z; As[kA + 3][mA] = a0.w;
        As[kA + 4][mA] = a1.x; As[kA + 5][mA] = a1.y;
        As[kA + 6][mA] = a1.z; As[kA + 7][mA] = a1.w;
#pragma unroll
        for (int j = 0; j < 8; ++j) Bs[kB0 + j][pB] = bsv[j];
        __syncthreads();

#pragma unroll
        for (int k = 0; k < 16; ++k) {
            float4 af0 = *(const float4*)&As[k][ty * 8];
            float4 af1 = *(const float4*)&As[k][ty * 8 + 4];
            ulonglong2 bv0 = *(const ulonglong2*)&Bs[k][tx * 8];
            ulonglong2 bv1 = *(const ulonglong2*)&Bs[k][tx * 8 + 4];
            unsigned long long bb0 = bv0.x, bb1 = bv0.y, bb2 = bv1.x, bb3 = bv1.y;
            float a[8] = {af0.x, af0.y, af0.z, af0.w, af1.x, af1.y, af1.z, af1.w};
#pragma unroll
            for (int m = 0; m < 8; ++m) {
                unsigned long long ap = dup2(a[m]);
                fma2(acc[m][0], ap, bb0);
                fma2(acc[m][1], ap, bb1);
                fma2(acc[m][2], ap, bb2);
                fma2(acc[m][3], ap, bb3);
            }
        }
        __syncthreads();
    }

    // Epilogue: + we0*ds + be, *alpha, residual, relu, store
    const float al = alpha[0];
    float* Ob = out + (size_t)b * Cch * HW;
    const int p0 = tx * 8;

    float dsv[8];
#pragma unroll
    for (int j = 0; j < 8; ++j) dsv[j] = s_ds[p0 + j];

#pragma unroll
    for (int i = 0; i < 8; ++i) {
        const int r  = ty * 8 + i;          // row within tile
        const int mg = mt * 128 + r;        // global output channel
        const float we0 = s_we0[r];
        const float be  = s_be[r];
        const float* Fp = Fb + (size_t)mg * HW + n0 + p0;
        float*       Op = Ob + (size_t)mg * HW + n0 + p0;
        float4 x0 = *(const float4*)Fp;
        float4 x1 = *(const float4*)(Fp + 4);
        float2 c0 = u2f(acc[i][0]);
        float2 c1 = u2f(acc[i][1]);
        float2 c2 = u2f(acc[i][2]);
        float2 c3 = u2f(acc[i][3]);
        float4 r0, r1;
        r0.x = fmaxf(fmaf(c0.x + fmaf(we0, dsv[0], be), al, x0.x), 0.f);
        r0.y = fmaxf(fmaf(c0.y + fmaf(we0, dsv[1], be), al, x0.y), 0.f);
        r0.z = fmaxf(fmaf(c1.x + fmaf(we0, dsv[2], be), al, x0.z), 0.f);
        r0.w = fmaxf(fmaf(c1.y + fmaf(we0, dsv[3], be), al, x0.w), 0.f);
        r1.x = fmaxf(fmaf(c2.x + fmaf(we0, dsv[4], be), al, x1.x), 0.f);
        r1.y = fmaxf(fmaf(c2.y + fmaf(we0, dsv[5], be), al, x1.y), 0.f);
        r1.z = fmaxf(fmaf(c3.x + fmaf(we0, dsv[6], be), al, x1.z), 0.f);
        r1.w = fmaxf(fmaf(c3.y + fmaf(we0, dsv[7], be), al, x1.w), 0.f);
        *(float4*)Op       = r0;
        *(float4*)(Op + 4) = r1;
    }
}

// ---------------------------------------------------------------------------
extern "C" void kernel_launch(void* const* d_in, const int* in_sizes, int n_in,
                              void* d_out, int out_size) {
    const float* feats  = (const float*)d_in[0];
    const float* P2     = (const float*)d_in[1];
    const float* w_disp = (const float*)d_in[2];
    const float* b_disp = (const float*)d_in[3];
    const float* w_ext  = (const float*)d_in[4];
    const float* b_ext  = (const float*)d_in[5];
    const float* alpha  = (const float*)d_in[6];
    float* out = (float*)d_out;

    prepA_kernel<<<256, 256>>>(w_ext);
    prep_kernel<<<Bsz * 12, dim3(160, 4)>>>(feats, P2, w_disp, b_disp);
    gemm_fused<<<dim3(HW / 128, MM / 128, Bsz), 256>>>(feats, w_ext, b_ext, alpha, out);
}

// round 4
// speedup vs baseline: 3.0526x; 2.5848x over previous
#include <cuda_runtime.h>
#include <cuda_bf16.h>
#include <cstdint>

#define Bsz 16
#define Cch 256
#define Hh 48
#define Ww 160
#define HW (Hh*Ww)          // 7680
#define MM 256
#define KK 256

// Scratch (device globals)
__device__ __nv_bfloat16 g_Whi[MM * KK];
__device__ __nv_bfloat16 g_Wlo[MM * KK];
__device__ float  g_part[32 * Bsz * HW];        // conv partials
__device__ float4 g_px[Bsz * HW];               // per-pixel (iy0, wy, dsamp, _)

// ---------------------------------------------------------------------------
// helpers
// ---------------------------------------------------------------------------
__device__ __forceinline__ uint32_t s2u(const void* p) {
    uint32_t a;
    asm("{ .reg .u64 t; cvta.to.shared.u64 t, %1; cvt.u32.u64 %0, t; }" : "=r"(a) : "l"(p));
    return a;
}
__device__ __forceinline__ void ldmatrix_x4(uint32_t& r0, uint32_t& r1, uint32_t& r2, uint32_t& r3, uint32_t a) {
    asm volatile("ldmatrix.sync.aligned.m8n8.x4.shared.b16 {%0,%1,%2,%3}, [%4];"
                 : "=r"(r0), "=r"(r1), "=r"(r2), "=r"(r3) : "r"(a));
}
__device__ __forceinline__ void ldmatrix_x2(uint32_t& r0, uint32_t& r1, uint32_t a) {
    asm volatile("ldmatrix.sync.aligned.m8n8.x2.shared.b16 {%0,%1}, [%2];"
                 : "=r"(r0), "=r"(r1) : "r"(a));
}
__device__ __forceinline__ void mma_bf16(float* c, const uint32_t* a, const uint32_t* b) {
    asm volatile("mma.sync.aligned.m16n8k16.row.col.f32.bf16.bf16.f32 "
                 "{%0,%1,%2,%3}, {%4,%5,%6,%7}, {%8,%9}, {%0,%1,%2,%3};"
                 : "+f"(c[0]), "+f"(c[1]), "+f"(c[2]), "+f"(c[3])
                 : "r"(a[0]), "r"(a[1]), "r"(a[2]), "r"(a[3]), "r"(b[0]), "r"(b[1]));
}

// smem layout (bytes): A rows padded to 48B (ldmatrix conflict-free)
#define OFF_A(buf) ((buf) * 24576)              // hi +0, lo +12288 (256 rows x 48B)
#define OFF_B(buf) (49152 + (buf) * 12288)      // hi +0, lo +6144  (128 rows x 48B)
#define OFF_O0 73728
#define OFF_O1 74240
#define OFF_WY 74752
#define OFF_DS 75264
#define OFF_WE 75776
#define OFF_BE 76800
#define SMEM_TOTAL 77824

// ---------------------------------------------------------------------------
// Kernel 0: split w_ext[:,1:] into bf16 hi/lo
// ---------------------------------------------------------------------------
__global__ void prepA_kernel(const float* __restrict__ w_ext) {
    int i = blockIdx.x * blockDim.x + threadIdx.x;
    if (i < MM * KK) {
        int m = i >> 8, c = i & 255;
        float w = w_ext[m * 257 + 1 + c];
        __nv_bfloat16 h = __float2bfloat16(w);
        __nv_bfloat16 l = __float2bfloat16(w - __bfloat162float(h));
        g_Whi[i] = h;
        g_Wlo[i] = l;
    }
}

// ---------------------------------------------------------------------------
// Kernel 1a: conv partials — one block per (4 rows, 8-channel chunk, batch)
// ---------------------------------------------------------------------------
__global__ void __launch_bounds__(160)
conv_part_kernel(const float* __restrict__ feats, const float* __restrict__ w_disp) {
    const int y0 = blockIdx.x * 4;
    const int cchunk = blockIdx.y;
    const int b = blockIdx.z;
    const int wx = threadIdx.x;

    __shared__ float sw[72];
    __shared__ float srow[6][Ww];
    if (wx < 72) sw[wx] = w_disp[cchunk * 72 + wx];

    float a0 = 0.f, a1 = 0.f, a2 = 0.f, a3 = 0.f;
    const float* Fb = feats + ((size_t)b * Cch + cchunk * 8) * HW;
    __syncthreads();

    for (int cc = 0; cc < 8; ++cc) {
        const float* Fc = Fb + (size_t)cc * HW;
#pragma unroll
        for (int r = 0; r < 6; ++r) {
            int yy = y0 - 1 + r;
            srow[r][wx] = (yy >= 0 && yy < Hh) ? Fc[yy * Ww + wx] : 0.f;
        }
        __syncthreads();
        float v[6][3];
#pragma unroll
        for (int r = 0; r < 6; ++r) {
            v[r][0] = (wx > 0)      ? srow[r][wx - 1] : 0.f;
            v[r][1] =                 srow[r][wx];
            v[r][2] = (wx < Ww - 1) ? srow[r][wx + 1] : 0.f;
        }
        const float* wc = &sw[cc * 9];
#pragma unroll
        for (int ky = 0; ky < 3; ++ky)
#pragma unroll
            for (int kx = 0; kx < 3; ++kx) {
                float wv = wc[ky * 3 + kx];
                a0 = fmaf(v[0 + ky][kx], wv, a0);
                a1 = fmaf(v[1 + ky][kx], wv, a1);
                a2 = fmaf(v[2 + ky][kx], wv, a2);
                a3 = fmaf(v[3 + ky][kx], wv, a3);
            }
        __syncthreads();
    }
    float* P = g_part + (size_t)cchunk * (Bsz * HW) + ((size_t)b * Hh + y0) * Ww + wx;
    P[0 * Ww] = a0; P[1 * Ww] = a1; P[2 * Ww] = a2; P[3 * Ww] = a3;
}

// ---------------------------------------------------------------------------
// Kernel 1b: reduce partials + scalar math -> g_px
// ---------------------------------------------------------------------------
__global__ void px_kernel(const float* __restrict__ P2, const float* __restrict__ b_disp) {
    int idx = blockIdx.x * 256 + threadIdx.x;
    int b = idx / HW;
    int rem = idx - b * HW;
    int y = rem / Ww;

    float a = 0.f;
#pragma unroll
    for (int j = 0; j < 32; ++j) a += g_part[(size_t)j * (Bsz * HW) + idx];

    const float fy = P2[b * 12 + 5] * 0.0625f;
    const float cy = P2[b * 12 + 6] * 0.0625f;
    const float Ty = P2[b * 12 + 7] * 0.0625f;
    const float denomD = fabsf(fy * 1.65f + Ty) + 1e-10f;
    const float ysb_den = 2.f * (1.65f - 0.5f * 1.535f);

    float d = tanhf(a + b_disp[0]);
    float disp = 0.1f * d;
    float ybase = -1.f + 2.f * (float)y / 47.f;
    float ysb = fmaxf(1.535f * ((float)y - cy) / ysb_den, 0.f) * (1.f / 24.f);
    float gy = ybase + ysb + disp;
    float iy = fminf(fmaxf((gy + 1.f) * 23.5f, 0.f), 47.f);
    float iy0f = floorf(iy);
    float wy = iy - iy0f;
    int iy0 = (int)iy0f;
    int iy1 = min(iy0 + 1, Hh - 1);
    float d0 = fmaxf(fy * 0.54f * ((float)iy0 - cy) / denomD, 0.f);
    float d1 = fmaxf(fy * 0.54f * ((float)iy1 - cy) / denomD, 0.f);
    float ds = (1.f - wy) * d0 + wy * d1;
    g_px[idx] = make_float4(iy0f, wy, ds, 0.f);
}

// ---------------------------------------------------------------------------
// Kernel 2: mma.sync bf16-split sampled-GEMM + epilogue.
// D[chan=256][px=128] per CTA; 8 warps, warp tile 64x64; K=256 in 16 ksteps.
// grid = (60, 1, 16), block = 256.
// ---------------------------------------------------------------------------
__global__ void __launch_bounds__(256)
gemm_mma(const float* __restrict__ feats,
         const float* __restrict__ w_ext,
         const float* __restrict__ b_ext,
         const float* __restrict__ alpha,
         float* __restrict__ out) {
    extern __shared__ char sm[];
    const uint32_t smb = s2u(sm);
    const int tid  = threadIdx.x;
    const int wid  = tid >> 5, lane = tid & 31;
    const int b    = blockIdx.z;
    const int n0   = blockIdx.x * 128;

    int*   s_o0 = (int*)(sm + OFF_O0);
    int*   s_o1 = (int*)(sm + OFF_O1);
    float* s_wy = (float*)(sm + OFF_WY);
    float* s_ds = (float*)(sm + OFF_DS);
    float* s_we = (float*)(sm + OFF_WE);
    float* s_be = (float*)(sm + OFF_BE);

    if (tid < 128) {
        float4 px = g_px[(size_t)b * HW + n0 + tid];
        int iy0 = (int)px.x;
        int iy1 = min(iy0 + 1, Hh - 1);
        int w = (n0 + tid) % Ww;
        s_o0[tid] = iy0 * Ww + w;
        s_o1[tid] = iy1 * Ww + w;
        s_wy[tid] = px.y;
        s_ds[tid] = px.z;
    }
    s_we[tid] = w_ext[tid * 257];
    s_be[tid] = b_ext[tid];
    __syncthreads();

    const float* Fb = feats + (size_t)b * Cch * HW;

    // ---- producer state ----
    const int gp  = tid >> 1;             // pixel 0..127
    const int gkh = (tid & 1) * 8;        // k-half within kstep
    const int go0 = s_o0[gp], go1 = s_o1[gp];
    const float gwy = s_wy[gp];

    uint4 rAh0, rAh1, rAl0, rAl1;         // A (weights) staging
    uint32_t rBh[4], rBl[4];              // B (Fsamp) staging

    auto load_regs = [&](int ks) {
        const int k0 = ks * 16;
        const __nv_bfloat16* wh = g_Whi + tid * 256 + k0;
        const __nv_bfloat16* wl = g_Wlo + tid * 256 + k0;
        rAh0 = *(const uint4*)(wh);
        rAh1 = *(const uint4*)(wh + 8);
        rAl0 = *(const uint4*)(wl);
        rAl1 = *(const uint4*)(wl + 8);
        const float* Fk = Fb + (size_t)(k0 + gkh) * HW;
#pragma unroll
        for (int j = 0; j < 8; j += 2) {
            float x0 = __ldg(Fk + (size_t)j * HW + go0);
            float y0v = __ldg(Fk + (size_t)j * HW + go1);
            float x1 = __ldg(Fk + (size_t)(j + 1) * HW + go0);
            float y1v = __ldg(Fk + (size_t)(j + 1) * HW + go1);
            float v0 = fmaf(gwy, y0v - x0, x0);
            float v1 = fmaf(gwy, y1v - x1, x1);
            __nv_bfloat16 h0 = __float2bfloat16(v0), h1 = __float2bfloat16(v1);
            __nv_bfloat16 l0 = __float2bfloat16(v0 - __bfloat162float(h0));
            __nv_bfloat16 l1 = __float2bfloat16(v1 - __bfloat162float(h1));
            __nv_bfloat162 hp = __nv_bfloat162(h0, h1);
            __nv_bfloat162 lp = __nv_bfloat162(l0, l1);
            rBh[j >> 1] = *(uint32_t*)&hp;
            rBl[j >> 1] = *(uint32_t*)&lp;
        }
    };
    auto store_smem = [&](int buf) {
        char* ah = sm + OFF_A(buf);
        char* al = ah + 12288;
        *(uint4*)(ah + tid * 48)      = rAh0;
        *(uint4*)(ah + tid * 48 + 16) = rAh1;
        *(uint4*)(al + tid * 48)      = rAl0;
        *(uint4*)(al + tid * 48 + 16) = rAl1;
        char* bh = sm + OFF_B(buf);
        char* bl = bh + 6144;
#pragma unroll
        for (int j = 0; j < 4; ++j) {
            *(uint32_t*)(bh + gp * 48 + (gkh + 2 * j) * 2) = rBh[j];
            *(uint32_t*)(bl + gp * 48 + (gkh + 2 * j) * 2) = rBl[j];
        }
    };

    // ---- consumer state ----
    const int cb = (wid >> 1) * 64;       // channel base
    const int pb = (wid & 1) * 64;        // pixel base
    const uint32_t aRow = (lane & 15), aHalf = (lane >> 4);
    const uint32_t bRow = (lane & 7),  bHalf = (lane >> 3) & 1;

    float acc[4][8][4];
#pragma unroll
    for (int i = 0; i < 4; ++i)
#pragma unroll
        for (int j = 0; j < 8; ++j)
#pragma unroll
            for (int q = 0; q < 4; ++q) acc[i][j][q] = 0.f;

    load_regs(0);
    store_smem(0);
    __syncthreads();

    for (int ks = 0; ks < 16; ++ks) {
        const int cur = ks & 1;
        if (ks < 15) load_regs(ks + 1);

        const uint32_t aBaseH = smb + OFF_A(cur)         + (cb + aRow) * 48 + aHalf * 16;
        const uint32_t aBaseL = aBaseH + 12288;
        const uint32_t bBaseH = smb + OFF_B(cur)         + (pb + bRow) * 48 + bHalf * 16;
        const uint32_t bBaseL = bBaseH + 6144;

        uint32_t aF[4][4], bF[8][2];
        // pass 1: A_hi x B_hi
#pragma unroll
        for (int mt = 0; mt < 4; ++mt)
            ldmatrix_x4(aF[mt][0], aF[mt][1], aF[mt][2], aF[mt][3], aBaseH + mt * 16 * 48);
#pragma unroll
        for (int nt = 0; nt < 8; ++nt)
            ldmatrix_x2(bF[nt][0], bF[nt][1], bBaseH + nt * 8 * 48);
#pragma unroll
        for (int mt = 0; mt < 4; ++mt)
#pragma unroll
            for (int nt = 0; nt < 8; ++nt) mma_bf16(acc[mt][nt], aF[mt], bF[nt]);
        // pass 2: A_hi x B_lo
#pragma unroll
        for (int nt = 0; nt < 8; ++nt)
            ldmatrix_x2(bF[nt][0], bF[nt][1], bBaseL + nt * 8 * 48);
#pragma unroll
        for (int mt = 0; mt < 4; ++mt)
#pragma unroll
            for (int nt = 0; nt < 8; ++nt) mma_bf16(acc[mt][nt], aF[mt], bF[nt]);
        // pass 3: A_lo x B_hi
#pragma unroll
        for (int mt = 0; mt < 4; ++mt)
            ldmatrix_x4(aF[mt][0], aF[mt][1], aF[mt][2], aF[mt][3], aBaseL + mt * 16 * 48);
#pragma unroll
        for (int nt = 0; nt < 8; ++nt)
            ldmatrix_x2(bF[nt][0], bF[nt][1], bBaseH + nt * 8 * 48);
#pragma unroll
        for (int mt = 0; mt < 4; ++mt)
#pragma unroll
            for (int nt = 0; nt < 8; ++nt) mma_bf16(acc[mt][nt], aF[mt], bF[nt]);

        __syncthreads();
        if (ks < 15) {
            store_smem((ks + 1) & 1);
            __syncthreads();
        }
    }

    // ---- epilogue: D[chan][px], float2 per (tile, row-half) ----
    const float al = alpha[0];
    float* Ob = out + (size_t)b * Cch * HW + n0;
    const float* Fr = Fb + n0;
    const int rr = lane >> 2;             // 0..7
    const int ccol = (lane & 3) * 2;      // 0,2,4,6

#pragma unroll
    for (int mt = 0; mt < 4; ++mt) {
#pragma unroll
        for (int nt = 0; nt < 8; ++nt) {
            const int pxl = pb + nt * 8 + ccol;       // local pixel
            const float ds0 = s_ds[pxl], ds1 = s_ds[pxl + 1];
#pragma unroll
            for (int h = 0; h < 2; ++h) {
                const int ch = cb + mt * 16 + rr + h * 8;
                const float we = s_we[ch], be = s_be[ch];
                float v0 = acc[mt][nt][2 * h + 0] + fmaf(we, ds0, be);
                float v1 = acc[mt][nt][2 * h + 1] + fmaf(we, ds1, be);
                const float2 x = __ldg((const float2*)(Fr + (size_t)ch * HW + pxl));
                float2 r;
                r.x = fmaxf(fmaf(v0, al, x.x), 0.f);
                r.y = fmaxf(fmaf(v1, al, x.y), 0.f);
                *(float2*)(Ob + (size_t)ch * HW + pxl) = r;
            }
        }
    }
}

// ---------------------------------------------------------------------------
extern "C" void kernel_launch(void* const* d_in, const int* in_sizes, int n_in,
                              void* d_out, int out_size) {
    const float* feats  = (const float*)d_in[0];
    const float* P2     = (const float*)d_in[1];
    const float* w_disp = (const float*)d_in[2];
    const float* b_disp = (const float*)d_in[3];
    const float* w_ext  = (const float*)d_in[4];
    const float* b_ext  = (const float*)d_in[5];
    const float* alpha  = (const float*)d_in[6];
    float* out = (float*)d_out;

    cudaFuncSetAttribute(gemm_mma, cudaFuncAttributeMaxDynamicSharedMemorySize, SMEM_TOTAL);

    prepA_kernel<<<256, 256>>>(w_ext);
    conv_part_kernel<<<dim3(12, 32, Bsz), 160>>>(feats, w_disp);
    px_kernel<<<Bsz * HW / 256, 256>>>(P2, b_disp);
    gemm_mma<<<dim3(HW / 128, 1, Bsz), 256, SMEM_TOTAL>>>(feats, w_ext, b_ext, alpha, out);
}

// round 5
// speedup vs baseline: 3.5709x; 1.1698x over previous
#include <cuda_runtime.h>
#include <cuda_bf16.h>
#include <cstdint>

#define Bsz 16
#define Cch 256
#define Hh 48
#define Ww 160
#define HW (Hh*Ww)          // 7680
#define MM 256
#define KK 256

// Scratch (device globals)
__device__ __nv_bfloat16 g_Whi[MM * KK];
__device__ __nv_bfloat16 g_Wlo[MM * KK];
__device__ __nv_bfloat16 g_Fhi[(size_t)Bsz * Cch * HW];   // 63MB blended features hi
__device__ __nv_bfloat16 g_Flo[(size_t)Bsz * Cch * HW];   // 63MB blended features lo
__device__ float  g_part[32 * Bsz * HW];                  // conv partials
__device__ float4 g_px[Bsz * HW];                         // per-pixel (iy0, wy, dsamp, _)

// ---------------------------------------------------------------------------
// helpers
// ---------------------------------------------------------------------------
__device__ __forceinline__ uint32_t s2u(const void* p) {
    uint32_t a;
    asm("{ .reg .u64 t; cvta.to.shared.u64 t, %1; cvt.u32.u64 %0, t; }" : "=r"(a) : "l"(p));
    return a;
}
__device__ __forceinline__ void ldmatrix_x4(uint32_t& r0, uint32_t& r1, uint32_t& r2, uint32_t& r3, uint32_t a) {
    asm volatile("ldmatrix.sync.aligned.m8n8.x4.shared.b16 {%0,%1,%2,%3}, [%4];"
                 : "=r"(r0), "=r"(r1), "=r"(r2), "=r"(r3) : "r"(a));
}
__device__ __forceinline__ void ldmatrix_x2_trans(uint32_t& r0, uint32_t& r1, uint32_t a) {
    asm volatile("ldmatrix.sync.aligned.m8n8.x2.trans.shared.b16 {%0,%1}, [%2];"
                 : "=r"(r0), "=r"(r1) : "r"(a));
}
__device__ __forceinline__ void mma_bf16(float* c, const uint32_t* a, const uint32_t* b) {
    asm volatile("mma.sync.aligned.m16n8k16.row.col.f32.bf16.bf16.f32 "
                 "{%0,%1,%2,%3}, {%4,%5,%6,%7}, {%8,%9}, {%0,%1,%2,%3};"
                 : "+f"(c[0]), "+f"(c[1]), "+f"(c[2]), "+f"(c[3])
                 : "r"(a[0]), "r"(a[1]), "r"(a[2]), "r"(a[3]), "r"(b[0]), "r"(b[1]));
}
__device__ __forceinline__ void cpasync16(uint32_t dst, const void* src) {
    asm volatile("cp.async.cg.shared.global [%0], [%1], 16;" :: "r"(dst), "l"(src) : "memory");
}
#define CP_COMMIT() asm volatile("cp.async.commit_group;" ::: "memory")
#define CP_WAIT2()  asm volatile("cp.async.wait_group 2;" ::: "memory")

// smem stage layout (bytes): per stage 33280
//   Ahi: 256 rows x 48B   (+0)        Alo: +12288
//   Bhi: 16 rows x 272B   (+24576)    Blo: +28928
#define STG 33280
#define OFF_DS 133120
#define OFF_WE 133632
#define OFF_BE 134656
#define SMEM_TOTAL 135680

// ---------------------------------------------------------------------------
// Kernel 0: split w_ext[:,1:] into bf16 hi/lo
// ---------------------------------------------------------------------------
__global__ void prepA_kernel(const float* __restrict__ w_ext) {
    int i = blockIdx.x * blockDim.x + threadIdx.x;
    if (i < MM * KK) {
        int m = i >> 8, c = i & 255;
        float w = w_ext[m * 257 + 1 + c];
        __nv_bfloat16 h = __float2bfloat16(w);
        __nv_bfloat16 l = __float2bfloat16(w - __bfloat162float(h));
        g_Whi[i] = h;
        g_Wlo[i] = l;
    }
}

// ---------------------------------------------------------------------------
// Kernel 1a: conv partials — one block per (4 rows, 8-channel chunk, batch)
// ---------------------------------------------------------------------------
__global__ void __launch_bounds__(160)
conv_part_kernel(const float* __restrict__ feats, const float* __restrict__ w_disp) {
    const int y0 = blockIdx.x * 4;
    const int cchunk = blockIdx.y;
    const int b = blockIdx.z;
    const int wx = threadIdx.x;

    __shared__ float sw[72];
    __shared__ float srow[6][Ww];
    if (wx < 72) sw[wx] = w_disp[cchunk * 72 + wx];

    float a0 = 0.f, a1 = 0.f, a2 = 0.f, a3 = 0.f;
    const float* Fb = feats + ((size_t)b * Cch + cchunk * 8) * HW;
    __syncthreads();

    for (int cc = 0; cc < 8; ++cc) {
        const float* Fc = Fb + (size_t)cc * HW;
#pragma unroll
        for (int r = 0; r < 6; ++r) {
            int yy = y0 - 1 + r;
            srow[r][wx] = (yy >= 0 && yy < Hh) ? Fc[yy * Ww + wx] : 0.f;
        }
        __syncthreads();
        float v[6][3];
#pragma unroll
        for (int r = 0; r < 6; ++r) {
            v[r][0] = (wx > 0)      ? srow[r][wx - 1] : 0.f;
            v[r][1] =                 srow[r][wx];
            v[r][2] = (wx < Ww - 1) ? srow[r][wx + 1] : 0.f;
        }
        const float* wc = &sw[cc * 9];
#pragma unroll
        for (int ky = 0; ky < 3; ++ky)
#pragma unroll
            for (int kx = 0; kx < 3; ++kx) {
                float wv = wc[ky * 3 + kx];
                a0 = fmaf(v[0 + ky][kx], wv, a0);
                a1 = fmaf(v[1 + ky][kx], wv, a1);
                a2 = fmaf(v[2 + ky][kx], wv, a2);
                a3 = fmaf(v[3 + ky][kx], wv, a3);
            }
        __syncthreads();
    }
    float* P = g_part + (size_t)cchunk * (Bsz * HW) + ((size_t)b * Hh + y0) * Ww + wx;
    P[0 * Ww] = a0; P[1 * Ww] = a1; P[2 * Ww] = a2; P[3 * Ww] = a3;
}

// ---------------------------------------------------------------------------
// Kernel 1b: reduce partials + scalar math -> g_px
// ---------------------------------------------------------------------------
__global__ void px_kernel(const float* __restrict__ P2, const float* __restrict__ b_disp) {
    int idx = blockIdx.x * 256 + threadIdx.x;
    int b = idx / HW;
    int rem = idx - b * HW;
    int y = rem / Ww;

    float a = 0.f;
#pragma unroll
    for (int j = 0; j < 32; ++j) a += g_part[(size_t)j * (Bsz * HW) + idx];

    const float fy = P2[b * 12 + 5] * 0.0625f;
    const float cy = P2[b * 12 + 6] * 0.0625f;
    const float Ty = P2[b * 12 + 7] * 0.0625f;
    const float denomD = fabsf(fy * 1.65f + Ty) + 1e-10f;
    const float ysb_den = 2.f * (1.65f - 0.5f * 1.535f);

    float d = tanhf(a + b_disp[0]);
    float disp = 0.1f * d;
    float ybase = -1.f + 2.f * (float)y / 47.f;
    float ysb = fmaxf(1.535f * ((float)y - cy) / ysb_den, 0.f) * (1.f / 24.f);
    float gy = ybase + ysb + disp;
    float iy = fminf(fmaxf((gy + 1.f) * 23.5f, 0.f), 47.f);
    float iy0f = floorf(iy);
    float wy = iy - iy0f;
    int iy0 = (int)iy0f;
    int iy1 = min(iy0 + 1, Hh - 1);
    float d0 = fmaxf(fy * 0.54f * ((float)iy0 - cy) / denomD, 0.f);
    float d1 = fmaxf(fy * 0.54f * ((float)iy1 - cy) / denomD, 0.f);
    float ds = (1.f - wy) * d0 + wy * d1;
    g_px[idx] = make_float4(iy0f, wy, ds, 0.f);
}

// ---------------------------------------------------------------------------
// Kernel 1c: materialize blended features as bf16 hi/lo: Fsamp[b][c][px]
// grid = (30, 64, 16), block = 256; each thread: 1 px, 4 channels
// ---------------------------------------------------------------------------
__global__ void __launch_bounds__(256)
sample_kernel(const float* __restrict__ feats) {
    const int px = blockIdx.x * 256 + threadIdx.x;
    const int c0 = blockIdx.y * 4;
    const int b  = blockIdx.z;

    float4 p = g_px[(size_t)b * HW + px];
    int iy0 = (int)p.x;
    int iy1 = min(iy0 + 1, Hh - 1);
    int w = px - (px / Ww) * Ww;
    const float wy = p.y;
    const int o0 = iy0 * Ww + w;
    const int o1 = iy1 * Ww + w;

    const float* F = feats + ((size_t)b * Cch + c0) * HW;
    const size_t ob = ((size_t)b * Cch + c0) * HW + px;
#pragma unroll
    for (int j = 0; j < 4; ++j) {
        float f0 = __ldg(F + (size_t)j * HW + o0);
        float f1 = __ldg(F + (size_t)j * HW + o1);
        float v = fmaf(wy, f1 - f0, f0);
        __nv_bfloat16 h = __float2bfloat16(v);
        __nv_bfloat16 l = __float2bfloat16(v - __bfloat162float(h));
        g_Fhi[ob + (size_t)j * HW] = h;
        g_Flo[ob + (size_t)j * HW] = l;
    }
}

// ---------------------------------------------------------------------------
// Kernel 2: cp.async-pipelined bf16-split GEMM + epilogue.
// D[chan=256][px=128] per CTA; 8 warps, warp tile 64x64; 16 ksteps, 4 stages.
// grid = (60, 1, 16), block = 256.
// ---------------------------------------------------------------------------
__global__ void __launch_bounds__(256)
gemm_mma(const float* __restrict__ feats,
         const float* __restrict__ w_ext,
         const float* __restrict__ b_ext,
         const float* __restrict__ alpha,
         float* __restrict__ out) {
    extern __shared__ char sm[];
    const uint32_t smb = s2u(sm);
    const int tid  = threadIdx.x;
    const int wid  = tid >> 5, lane = tid & 31;
    const int b    = blockIdx.z;
    const int n0   = blockIdx.x * 128;

    float* s_ds = (float*)(sm + OFF_DS);
    float* s_we = (float*)(sm + OFF_WE);
    float* s_be = (float*)(sm + OFF_BE);

    if (tid < 128) s_ds[tid] = g_px[(size_t)b * HW + n0 + tid].z;
    s_we[tid] = w_ext[tid * 257];
    s_be[tid] = b_ext[tid];

    // cp.async producer: per stage 6 x 16B chunks per thread
    auto issue = [&](int ks) {
        const uint32_t base = smb + (ks & 3) * STG;
#pragma unroll
        for (int i = 0; i < 2; ++i) {
            int c = tid + i * 256;
            int row = c >> 1, seg = c & 1;
            const char* sh = (const char*)g_Whi + row * 512 + ks * 32 + seg * 16;
            const char* sl = (const char*)g_Wlo + row * 512 + ks * 32 + seg * 16;
            cpasync16(base + row * 48 + seg * 16, sh);
            cpasync16(base + 12288 + row * 48 + seg * 16, sl);
        }
#pragma unroll
        for (int i = 0; i < 2; ++i) {
            int c = tid + i * 256;
            int half = c >> 8, row = (c >> 4) & 15, seg = c & 15;
            const __nv_bfloat16* srcA = half ? g_Flo : g_Fhi;
            const char* src = (const char*)(srcA + ((size_t)(b * Cch + ks * 16 + row)) * HW + n0) + seg * 16;
            cpasync16(base + 24576 + half * 4352 + row * 272 + seg * 16, src);
        }
    };

    issue(0); CP_COMMIT();
    issue(1); CP_COMMIT();
    issue(2); CP_COMMIT();

    // consumer mapping
    const int cb = (wid >> 1) * 64;       // channel base
    const int pb = (wid & 1) * 64;        // pixel base
    const uint32_t aOff = (cb + (lane & 15)) * 48 + ((lane >> 4) * 16);
    const uint32_t bOff = 24576 + (lane & 15) * 272 + pb * 2;

    float acc[4][8][4];
#pragma unroll
    for (int i = 0; i < 4; ++i)
#pragma unroll
        for (int j = 0; j < 8; ++j)
#pragma unroll
            for (int q = 0; q < 4; ++q) acc[i][j][q] = 0.f;

    for (int ks = 0; ks < 16; ++ks) {
        CP_WAIT2();
        __syncthreads();
        const uint32_t base = smb + (ks & 3) * STG;
        const uint32_t aBaseH = base + aOff;
        const uint32_t aBaseL = aBaseH + 12288;
        const uint32_t bBaseH = base + bOff;
        const uint32_t bBaseL = bBaseH + 4352;

        uint32_t aH[4][4], aL[4][4], bF[8][2];
#pragma unroll
        for (int mt = 0; mt < 4; ++mt) {
            ldmatrix_x4(aH[mt][0], aH[mt][1], aH[mt][2], aH[mt][3], aBaseH + mt * 768);
            ldmatrix_x4(aL[mt][0], aL[mt][1], aL[mt][2], aL[mt][3], aBaseL + mt * 768);
        }
        // B hi: pass 1 (Ah x Bh) and pass 3 (Al x Bh)
#pragma unroll
        for (int nt = 0; nt < 8; ++nt)
            ldmatrix_x2_trans(bF[nt][0], bF[nt][1], bBaseH + nt * 16);
#pragma unroll
        for (int mt = 0; mt < 4; ++mt)
#pragma unroll
            for (int nt = 0; nt < 8; ++nt) mma_bf16(acc[mt][nt], aH[mt], bF[nt]);
#pragma unroll
        for (int mt = 0; mt < 4; ++mt)
#pragma unroll
            for (int nt = 0; nt < 8; ++nt) mma_bf16(acc[mt][nt], aL[mt], bF[nt]);
        // B lo: pass 2 (Ah x Bl)
#pragma unroll
        for (int nt = 0; nt < 8; ++nt)
            ldmatrix_x2_trans(bF[nt][0], bF[nt][1], bBaseL + nt * 16);
#pragma unroll
        for (int mt = 0; mt < 4; ++mt)
#pragma unroll
            for (int nt = 0; nt < 8; ++nt) mma_bf16(acc[mt][nt], aH[mt], bF[nt]);

        if (ks + 3 < 16) issue(ks + 3);
        CP_COMMIT();
    }

    // ---- epilogue: D[chan][px] ----
    const float al = alpha[0];
    const float* Fb = feats + (size_t)b * Cch * HW;
    float* Ob = out + (size_t)b * Cch * HW + n0;
    const float* Fr = Fb + n0;
    const int rr = lane >> 2;
    const int ccol = (lane & 3) * 2;

#pragma unroll
    for (int mt = 0; mt < 4; ++mt) {
#pragma unroll
        for (int nt = 0; nt < 8; ++nt) {
            const int pxl = pb + nt * 8 + ccol;
            const float ds0 = s_ds[pxl], ds1 = s_ds[pxl + 1];
#pragma unroll
            for (int h = 0; h < 2; ++h) {
                const int ch = cb + mt * 16 + rr + h * 8;
                const float we = s_we[ch], be = s_be[ch];
                float v0 = acc[mt][nt][2 * h + 0] + fmaf(we, ds0, be);
                float v1 = acc[mt][nt][2 * h + 1] + fmaf(we, ds1, be);
                const float2 x = __ldg((const float2*)(Fr + (size_t)ch * HW + pxl));
                float2 r;
                r.x = fmaxf(fmaf(v0, al, x.x), 0.f);
                r.y = fmaxf(fmaf(v1, al, x.y), 0.f);
                *(float2*)(Ob + (size_t)ch * HW + pxl) = r;
            }
        }
    }
}

// ---------------------------------------------------------------------------
extern "C" void kernel_launch(void* const* d_in, const int* in_sizes, int n_in,
                              void* d_out, int out_size) {
    const float* feats  = (const float*)d_in[0];
    const float* P2     = (const float*)d_in[1];
    const float* w_disp = (const float*)d_in[2];
    const float* b_disp = (const float*)d_in[3];
    const float* w_ext  = (const float*)d_in[4];
    const float* b_ext  = (const float*)d_in[5];
    const float* alpha  = (const float*)d_in[6];
    float* out = (float*)d_out;

    cudaFuncSetAttribute(gemm_mma, cudaFuncAttributeMaxDynamicSharedMemorySize, SMEM_TOTAL);

    prepA_kernel<<<256, 256>>>(w_ext);
    conv_part_kernel<<<dim3(12, 32, Bsz), 160>>>(feats, w_disp);
    px_kernel<<<Bsz * HW / 256, 256>>>(P2, b_disp);
    sample_kernel<<<dim3(HW / 256, Cch / 4, Bsz), 256>>>(feats);
    gemm_mma<<<dim3(HW / 128, 1, Bsz), 256, SMEM_TOTAL>>>(feats, w_ext, b_ext, alpha, out);
}

// round 6
// speedup vs baseline: 5.0423x; 1.4121x over previous
#include <cuda_runtime.h>
#include <cuda_bf16.h>
#include <cuda_fp16.h>
#include <cstdint>

#define Bsz 16
#define Cch 256
#define Hh 48
#define Ww 160
#define HW (Hh*Ww)          // 7680
#define MM 256
#define KK 256

// Scratch (device globals)
__device__ __half g_Wh[MM * KK];                      // fp16 weights
__device__ __half g_Fh[(size_t)Bsz * Cch * HW];       // 63MB blended features fp16
__device__ float  g_part[32 * Bsz * HW];              // conv partials
__device__ float4 g_px[Bsz * HW];                     // per-pixel (iy0, wy, dsamp, _)

// ---------------------------------------------------------------------------
// helpers
// ---------------------------------------------------------------------------
__device__ __forceinline__ uint32_t s2u(const void* p) {
    uint32_t a;
    asm("{ .reg .u64 t; cvta.to.shared.u64 t, %1; cvt.u32.u64 %0, t; }" : "=r"(a) : "l"(p));
    return a;
}
__device__ __forceinline__ void ldmatrix_x4(uint32_t& r0, uint32_t& r1, uint32_t& r2, uint32_t& r3, uint32_t a) {
    asm volatile("ldmatrix.sync.aligned.m8n8.x4.shared.b16 {%0,%1,%2,%3}, [%4];"
                 : "=r"(r0), "=r"(r1), "=r"(r2), "=r"(r3) : "r"(a));
}
__device__ __forceinline__ void ldmatrix_x2_trans(uint32_t& r0, uint32_t& r1, uint32_t a) {
    asm volatile("ldmatrix.sync.aligned.m8n8.x2.trans.shared.b16 {%0,%1}, [%2];"
                 : "=r"(r0), "=r"(r1) : "r"(a));
}
__device__ __forceinline__ void mma_f16(float* c, const uint32_t* a, const uint32_t* b) {
    asm volatile("mma.sync.aligned.m16n8k16.row.col.f32.f16.f16.f32 "
                 "{%0,%1,%2,%3}, {%4,%5,%6,%7}, {%8,%9}, {%0,%1,%2,%3};"
                 : "+f"(c[0]), "+f"(c[1]), "+f"(c[2]), "+f"(c[3])
                 : "r"(a[0]), "r"(a[1]), "r"(a[2]), "r"(a[3]), "r"(b[0]), "r"(b[1]));
}
__device__ __forceinline__ void cpasync16(uint32_t dst, const void* src) {
    asm volatile("cp.async.cg.shared.global [%0], [%1], 16;" :: "r"(dst), "l"(src) : "memory");
}
#define CP_COMMIT() asm volatile("cp.async.commit_group;" ::: "memory")
#define CP_WAIT2()  asm volatile("cp.async.wait_group 2;" ::: "memory")

// smem stage layout (bytes), BK=32:
//   A: 256 rows x 64B data, 80B pitch  (+0,     20480 B)
//   B: 32  rows x 256B data, 272B pitch (+20480, 8704 B)
#define ABYTES 20480
#define STG    29184
#define OFF_DS (4 * STG)
#define OFF_WE (OFF_DS + 512)
#define OFF_BE (OFF_WE + 1024)
#define SMEM_TOTAL (OFF_BE + 1024)

// ---------------------------------------------------------------------------
// Kernel 0: w_ext[:,1:] -> fp16
// ---------------------------------------------------------------------------
__global__ void prepA_kernel(const float* __restrict__ w_ext) {
    int i = blockIdx.x * blockDim.x + threadIdx.x;
    if (i < MM * KK) {
        int m = i >> 8, c = i & 255;
        g_Wh[i] = __float2half(w_ext[m * 257 + 1 + c]);
    }
}

// ---------------------------------------------------------------------------
// Kernel 1a: conv partials — one block per (4 rows, 8-channel chunk, batch)
// ---------------------------------------------------------------------------
__global__ void __launch_bounds__(160)
conv_part_kernel(const float* __restrict__ feats, const float* __restrict__ w_disp) {
    const int y0 = blockIdx.x * 4;
    const int cchunk = blockIdx.y;
    const int b = blockIdx.z;
    const int wx = threadIdx.x;

    __shared__ float sw[72];
    __shared__ float srow[6][Ww];
    if (wx < 72) sw[wx] = w_disp[cchunk * 72 + wx];

    float a0 = 0.f, a1 = 0.f, a2 = 0.f, a3 = 0.f;
    const float* Fb = feats + ((size_t)b * Cch + cchunk * 8) * HW;
    __syncthreads();

    for (int cc = 0; cc < 8; ++cc) {
        const float* Fc = Fb + (size_t)cc * HW;
#pragma unroll
        for (int r = 0; r < 6; ++r) {
            int yy = y0 - 1 + r;
            srow[r][wx] = (yy >= 0 && yy < Hh) ? Fc[yy * Ww + wx] : 0.f;
        }
        __syncthreads();
        float v[6][3];
#pragma unroll
        for (int r = 0; r < 6; ++r) {
            v[r][0] = (wx > 0)      ? srow[r][wx - 1] : 0.f;
            v[r][1] =                 srow[r][wx];
            v[r][2] = (wx < Ww - 1) ? srow[r][wx + 1] : 0.f;
        }
        const float* wc = &sw[cc * 9];
#pragma unroll
        for (int ky = 0; ky < 3; ++ky)
#pragma unroll
            for (int kx = 0; kx < 3; ++kx) {
                float wv = wc[ky * 3 + kx];
                a0 = fmaf(v[0 + ky][kx], wv, a0);
                a1 = fmaf(v[1 + ky][kx], wv, a1);
                a2 = fmaf(v[2 + ky][kx], wv, a2);
                a3 = fmaf(v[3 + ky][kx], wv, a3);
            }
        __syncthreads();
    }
    float* P = g_part + (size_t)cchunk * (Bsz * HW) + ((size_t)b * Hh + y0) * Ww + wx;
    P[0 * Ww] = a0; P[1 * Ww] = a1; P[2 * Ww] = a2; P[3 * Ww] = a3;
}

// ---------------------------------------------------------------------------
// Kernel 1b: reduce partials + scalar math -> g_px
// ---------------------------------------------------------------------------
__global__ void px_kernel(const float* __restrict__ P2, const float* __restrict__ b_disp) {
    int idx = blockIdx.x * 256 + threadIdx.x;
    int b = idx / HW;
    int rem = idx - b * HW;
    int y = rem / Ww;

    float a = 0.f;
#pragma unroll
    for (int j = 0; j < 32; ++j) a += g_part[(size_t)j * (Bsz * HW) + idx];

    const float fy = P2[b * 12 + 5] * 0.0625f;
    const float cy = P2[b * 12 + 6] * 0.0625f;
    const float Ty = P2[b * 12 + 7] * 0.0625f;
    const float denomD = fabsf(fy * 1.65f + Ty) + 1e-10f;
    const float ysb_den = 2.f * (1.65f - 0.5f * 1.535f);

    float d = tanhf(a + b_disp[0]);
    float disp = 0.1f * d;
    float ybase = -1.f + 2.f * (float)y / 47.f;
    float ysb = fmaxf(1.535f * ((float)y - cy) / ysb_den, 0.f) * (1.f / 24.f);
    float gy = ybase + ysb + disp;
    float iy = fminf(fmaxf((gy + 1.f) * 23.5f, 0.f), 47.f);
    float iy0f = floorf(iy);
    float wy = iy - iy0f;
    int iy0 = (int)iy0f;
    int iy1 = min(iy0 + 1, Hh - 1);
    float d0 = fmaxf(fy * 0.54f * ((float)iy0 - cy) / denomD, 0.f);
    float d1 = fmaxf(fy * 0.54f * ((float)iy1 - cy) / denomD, 0.f);
    float ds = (1.f - wy) * d0 + wy * d1;
    g_px[idx] = make_float4(iy0f, wy, ds, 0.f);
}

// ---------------------------------------------------------------------------
// Kernel 1c: materialize blended features fp16: Fsamp[b][c][px]
// grid = (30, 64, 16), block = 256; each thread: 1 px, 4 channels
// ---------------------------------------------------------------------------
__global__ void __launch_bounds__(256)
sample_kernel(const float* __restrict__ feats) {
    const int px = blockIdx.x * 256 + threadIdx.x;
    const int c0 = blockIdx.y * 4;
    const int b  = blockIdx.z;

    float4 p = g_px[(size_t)b * HW + px];
    int iy0 = (int)p.x;
    int iy1 = min(iy0 + 1, Hh - 1);
    int w = px - (px / Ww) * Ww;
    const float wy = p.y;
    const int o0 = iy0 * Ww + w;
    const int o1 = iy1 * Ww + w;

    const float* F = feats + ((size_t)b * Cch + c0) * HW;
    const size_t ob = ((size_t)b * Cch + c0) * HW + px;
#pragma unroll
    for (int j = 0; j < 4; ++j) {
        float f0 = __ldg(F + (size_t)j * HW + o0);
        float f1 = __ldg(F + (size_t)j * HW + o1);
        float v = fmaf(wy, f1 - f0, f0);
        g_Fh[ob + (size_t)j * HW] = __float2half(v);
    }
}

// ---------------------------------------------------------------------------
// Kernel 2: cp.async-pipelined fp16 GEMM + epilogue (single pass).
// D[chan=256][px=128] per CTA; 8 warps, warp tile 64x64; 8 ksteps (BK=32).
// grid = (60, 1, 16), block = 256.
// ---------------------------------------------------------------------------
__global__ void __launch_bounds__(256)
gemm_mma(const float* __restrict__ feats,
         const float* __restrict__ w_ext,
         const float* __restrict__ b_ext,
         const float* __restrict__ alpha,
         float* __restrict__ out) {
    extern __shared__ char sm[];
    const uint32_t smb = s2u(sm);
    const int tid  = threadIdx.x;
    const int wid  = tid >> 5, lane = tid & 31;
    const int b    = blockIdx.z;
    const int n0   = blockIdx.x * 128;

    float* s_ds = (float*)(sm + OFF_DS);
    float* s_we = (float*)(sm + OFF_WE);
    float* s_be = (float*)(sm + OFF_BE);

    if (tid < 128) s_ds[tid] = g_px[(size_t)b * HW + n0 + tid].z;
    s_we[tid] = w_ext[tid * 257];
    s_be[tid] = b_ext[tid];

    // producer: per stage, A: 4 chunks/thread, B: 2 chunks/thread (16B each)
    auto issue = [&](int ks) {
        const uint32_t base = smb + (ks & 3) * STG;
#pragma unroll
        for (int i = 0; i < 4; ++i) {
            int c = tid + i * 256;
            int row = c >> 2, seg = c & 3;                 // 256 rows x 4 segs
            cpasync16(base + row * 80 + seg * 16,
                      (const char*)g_Wh + row * 512 + ks * 64 + seg * 16);
        }
#pragma unroll
        for (int i = 0; i < 2; ++i) {
            int c = tid + i * 256;
            int row = c >> 4, seg = c & 15;                // 32 rows x 16 segs
            cpasync16(base + ABYTES + row * 272 + seg * 16,
                      (const char*)(g_Fh + ((size_t)(b * Cch + ks * 32 + row)) * HW + n0) + seg * 16);
        }
    };

    issue(0); CP_COMMIT();
    issue(1); CP_COMMIT();
    issue(2); CP_COMMIT();

    // consumer mapping
    const int cb = (wid >> 1) * 64;       // channel base
    const int pb = (wid & 1) * 64;        // pixel base
    const uint32_t aOff = (cb + (lane & 15)) * 80 + ((lane >> 4) * 16);
    const uint32_t bOff = ABYTES + (lane & 15) * 272 + pb * 2;

    float acc[4][8][4];
#pragma unroll
    for (int i = 0; i < 4; ++i)
#pragma unroll
        for (int j = 0; j < 8; ++j)
#pragma unroll
            for (int q = 0; q < 4; ++q) acc[i][j][q] = 0.f;

    for (int ks = 0; ks < 8; ++ks) {
        CP_WAIT2();
        __syncthreads();
        const uint32_t base = smb + (ks & 3) * STG;
#pragma unroll
        for (int ksub = 0; ksub < 2; ++ksub) {
            const uint32_t aBase = base + aOff + ksub * 32;
            const uint32_t bBase = base + bOff + ksub * 16 * 272;
            uint32_t aF[4][4], bF[8][2];
#pragma unroll
            for (int mt = 0; mt < 4; ++mt)
                ldmatrix_x4(aF[mt][0], aF[mt][1], aF[mt][2], aF[mt][3], aBase + mt * 16 * 80);
#pragma unroll
            for (int nt = 0; nt < 8; ++nt)
                ldmatrix_x2_trans(bF[nt][0], bF[nt][1], bBase + nt * 16);
#pragma unroll
            for (int mt = 0; mt < 4; ++mt)
#pragma unroll
                for (int nt = 0; nt < 8; ++nt) mma_f16(acc[mt][nt], aF[mt], bF[nt]);
        }
        if (ks + 3 < 8) issue(ks + 3);
        CP_COMMIT();
    }

    // ---- epilogue: D[chan][px] ----
    const float al = alpha[0];
    const float* Fb = feats + (size_t)b * Cch * HW;
    float* Ob = out + (size_t)b * Cch * HW + n0;
    const float* Fr = Fb + n0;
    const int rr = lane >> 2;
    const int ccol = (lane & 3) * 2;

#pragma unroll
    for (int mt = 0; mt < 4; ++mt) {
#pragma unroll
        for (int nt = 0; nt < 8; ++nt) {
            const int pxl = pb + nt * 8 + ccol;
            const float ds0 = s_ds[pxl], ds1 = s_ds[pxl + 1];
#pragma unroll
            for (int h = 0; h < 2; ++h) {
                const int ch = cb + mt * 16 + rr + h * 8;
                const float we = s_we[ch], be = s_be[ch];
                float v0 = acc[mt][nt][2 * h + 0] + fmaf(we, ds0, be);
                float v1 = acc[mt][nt][2 * h + 1] + fmaf(we, ds1, be);
                const float2 x = __ldg((const float2*)(Fr + (size_t)ch * HW + pxl));
                float2 r;
                r.x = fmaxf(fmaf(v0, al, x.x), 0.f);
                r.y = fmaxf(fmaf(v1, al, x.y), 0.f);
                *(float2*)(Ob + (size_t)ch * HW + pxl) = r;
            }
        }
    }
}

// ---------------------------------------------------------------------------
extern "C" void kernel_launch(void* const* d_in, const int* in_sizes, int n_in,
                              void* d_out, int out_size) {
    const float* feats  = (const float*)d_in[0];
    const float* P2     = (const float*)d_in[1];
    const float* w_disp = (const float*)d_in[2];
    const float* b_disp = (const float*)d_in[3];
    const float* w_ext  = (const float*)d_in[4];
    const float* b_ext  = (const float*)d_in[5];
    const float* alpha  = (const float*)d_in[6];
    float* out = (float*)d_out;

    cudaFuncSetAttribute(gemm_mma, cudaFuncAttributeMaxDynamicSharedMemorySize, SMEM_TOTAL);

    prepA_kernel<<<256, 256>>>(w_ext);
    conv_part_kernel<<<dim3(12, 32, Bsz), 160>>>(feats, w_disp);
    px_kernel<<<Bsz * HW / 256, 256>>>(P2, b_disp);
    sample_kernel<<<dim3(HW / 256, Cch / 4, Bsz), 256>>>(feats);
    gemm_mma<<<dim3(HW / 128, 1, Bsz), 256, SMEM_TOTAL>>>(feats, w_ext, b_ext, alpha, out);
}